// round 1
// baseline (speedup 1.0000x reference)
#include <cuda_runtime.h>
#include <cuda_bf16.h>
#include <math.h>

// ---------------------------------------------------------------------------
// VisLSTM: emb gather + img proj -> 49-step LSTM (batch 512, hidden 1024)
//          -> vocab projection (32000)
//
// Key structure: x_t @ W_ih^T precomputed for ALL timesteps in one big GEMM
// (25088 x 4096 x 1024); only h @ W_hh^T (512 x 4096 x 1024) is sequential.
// ---------------------------------------------------------------------------

#define NB    512
#define TT    48
#define SEQ   49            // T+1
#define EMBD  1024
#define HID   1024
#define G4    4096          // 4*HID
#define IMGD  4096
#define VOC   32000

// Scratch (static device globals; allocation-free per harness rules)
__device__ float g_X [(size_t)SEQ * NB * EMBD];     // [49, 512, 1024]
__device__ float g_GX[(size_t)SEQ * NB * G4];       // [49, 512, 4096] = X @ W_ih^T + b_ih
__device__ float g_EI[(size_t)NB * HID];            // img proj
__device__ float g_HW[(size_t)NB * G4];             // h @ W_hh^T + b_hh
__device__ float g_h [(size_t)NB * HID];
__device__ float g_c [(size_t)NB * HID];

// ---------------------------------------------------------------------------
// GEMM: C[M,N] = A[M,K] @ B[N,K]^T + bias[N]
// Requires M%128==0, N%128==0, K%8==0 (true for every call here).
// 128x128 block tile, BK=8, 256 threads, 8x8 per thread.
// ---------------------------------------------------------------------------
__global__ __launch_bounds__(256, 2)
void sgemm_nt_bias(const float* __restrict__ A, const float* __restrict__ B,
                   const float* __restrict__ bias, float* __restrict__ C,
                   int M, int N, int K)
{
    const int BM = 128, BN = 128, BK = 8, TM = 8, TN = 8;
    __shared__ float As[BK][BM];
    __shared__ float Bs[BK][BN];

    const int tid  = threadIdx.x;
    const int brow = blockIdx.y * BM;
    const int bcol = blockIdx.x * BN;

    const int trow = (tid / 16) * TM;   // 0..120
    const int tcol = (tid % 16) * TN;   // 0..120

    // global load mapping: one float4 per thread per tile per operand
    const int a_row = tid >> 1;          // 0..127
    const int a_kc  = (tid & 1) * 4;     // 0 or 4

    float acc[TM][TN];
    #pragma unroll
    for (int i = 0; i < TM; i++)
        #pragma unroll
        for (int j = 0; j < TN; j++) acc[i][j] = 0.f;

    const float* Aptr = A + (size_t)(brow + a_row) * K + a_kc;
    const float* Bptr = B + (size_t)(bcol + a_row) * K + a_kc;

    for (int k0 = 0; k0 < K; k0 += BK) {
        float4 av = *reinterpret_cast<const float4*>(Aptr + k0);
        float4 bv = *reinterpret_cast<const float4*>(Bptr + k0);
        As[a_kc + 0][a_row] = av.x;
        As[a_kc + 1][a_row] = av.y;
        As[a_kc + 2][a_row] = av.z;
        As[a_kc + 3][a_row] = av.w;
        Bs[a_kc + 0][a_row] = bv.x;
        Bs[a_kc + 1][a_row] = bv.y;
        Bs[a_kc + 2][a_row] = bv.z;
        Bs[a_kc + 3][a_row] = bv.w;
        __syncthreads();

        #pragma unroll
        for (int k = 0; k < BK; k++) {
            float ar[TM], br[TN];
            #pragma unroll
            for (int i = 0; i < TM; i++) ar[i] = As[k][trow + i];
            #pragma unroll
            for (int j = 0; j < TN; j++) br[j] = Bs[k][tcol + j];
            #pragma unroll
            for (int i = 0; i < TM; i++)
                #pragma unroll
                for (int j = 0; j < TN; j++)
                    acc[i][j] = fmaf(ar[i], br[j], acc[i][j]);
        }
        __syncthreads();
    }

    // epilogue
    float bvals[TN];
    #pragma unroll
    for (int j = 0; j < TN; j++)
        bvals[j] = bias ? bias[bcol + tcol + j] : 0.f;

    #pragma unroll
    for (int i = 0; i < TM; i++) {
        float* crow = C + (size_t)(brow + trow + i) * N + bcol + tcol;
        float4 v0 = make_float4(acc[i][0] + bvals[0], acc[i][1] + bvals[1],
                                acc[i][2] + bvals[2], acc[i][3] + bvals[3]);
        float4 v1 = make_float4(acc[i][4] + bvals[4], acc[i][5] + bvals[5],
                                acc[i][6] + bvals[6], acc[i][7] + bvals[7]);
        reinterpret_cast<float4*>(crow)[0] = v0;
        reinterpret_cast<float4*>(crow)[1] = v1;
    }
}

// ---------------------------------------------------------------------------
// Build the input sequence X[49,512,1024]:
//   slot == img_slot       -> EI[n]        (img_slot = fw ? 0 : 48)
//   else                   -> emb[questions[n][t]] with t = fw ? slot-1 : slot
// ---------------------------------------------------------------------------
__global__ void assemble_X(const int* __restrict__ questions,
                           const float* __restrict__ emb,
                           const float* __restrict__ EI,
                           const int* __restrict__ first_words,
                           float* __restrict__ X)
{
    const int slot = blockIdx.x;   // 0..48
    const int n    = blockIdx.y;   // 0..511
    const int fw   = (*first_words) != 0;
    const int img_slot = fw ? 0 : TT;

    const float* src;
    if (slot == img_slot) {
        src = EI + (size_t)n * HID;
    } else {
        const int t = fw ? (slot - 1) : slot;
        const int q = questions[n * TT + t];
        src = emb + (size_t)q * EMBD;
    }
    float4 v = reinterpret_cast<const float4*>(src)[threadIdx.x];
    reinterpret_cast<float4*>(X + ((size_t)slot * NB + n) * EMBD)[threadIdx.x] = v;
}

__global__ void zero_hc(float* __restrict__ h, float* __restrict__ c)
{
    int i = blockIdx.x * blockDim.x + threadIdx.x;
    h[i] = 0.f;
    c[i] = 0.f;
}

// ---------------------------------------------------------------------------
// LSTM pointwise cell: gates = GX_t + HW (both hold their bias already)
// torch gate order: i, f, g, o as 4 chunks of HID
// ---------------------------------------------------------------------------
__global__ void lstm_cell(const float* __restrict__ GX_t,
                          const float* __restrict__ HW,
                          float* __restrict__ c, float* __restrict__ h,
                          float* __restrict__ hs_out, int t)
{
    const int idx = blockIdx.x * blockDim.x + threadIdx.x;   // 0 .. 512*1024-1
    const int n = idx >> 10;
    const int j = idx & 1023;
    const size_t base = (size_t)n * G4;

    const float gi = GX_t[base + j]           + HW[base + j];
    const float gf = GX_t[base + HID + j]     + HW[base + HID + j];
    const float gg = GX_t[base + 2 * HID + j] + HW[base + 2 * HID + j];
    const float go = GX_t[base + 3 * HID + j] + HW[base + 3 * HID + j];

    const float i_ = 1.f / (1.f + expf(-gi));
    const float f_ = 1.f / (1.f + expf(-gf));
    const float g_ = tanhf(gg);
    const float o_ = 1.f / (1.f + expf(-go));

    const float cc = f_ * c[idx] + i_ * g_;
    const float hh = o_ * tanhf(cc);
    c[idx] = cc;
    h[idx] = hh;
    hs_out[((size_t)n * SEQ + t) * HID + j] = hh;
}

// ---------------------------------------------------------------------------
// Launch
// ---------------------------------------------------------------------------
extern "C" void kernel_launch(void* const* d_in, const int* in_sizes, int n_in,
                              void* d_out, int out_size)
{
    const int*   questions = (const int*)  d_in[0];   // [512,48]
    const float* img_feat  = (const float*)d_in[1];   // [512,4096]
    const float* emb       = (const float*)d_in[2];   // [32000,1024]
    const float* W_img     = (const float*)d_in[3];   // [1024,4096]
    const float* b_img     = (const float*)d_in[4];   // [1024]
    const float* W_ih      = (const float*)d_in[5];   // [4096,1024]
    const float* W_hh      = (const float*)d_in[6];   // [4096,1024]
    const float* b_ih      = (const float*)d_in[7];   // [4096]
    const float* b_hh      = (const float*)d_in[8];   // [4096]
    const float* W_out     = (const float*)d_in[9];   // [32000,1024]
    const float* b_out     = (const float*)d_in[10];  // [32000]
    const int*   first_w   = (const int*)  d_in[11];  // scalar

    float* out    = (float*)d_out;                        // [512,32000]
    float* hs_out = out + (size_t)NB * VOC;               // [512,49,1024]

    float *X, *GX, *EI, *HW, *h, *c;
    cudaGetSymbolAddress((void**)&X,  g_X);
    cudaGetSymbolAddress((void**)&GX, g_GX);
    cudaGetSymbolAddress((void**)&EI, g_EI);
    cudaGetSymbolAddress((void**)&HW, g_HW);
    cudaGetSymbolAddress((void**)&h,  g_h);
    cudaGetSymbolAddress((void**)&c,  g_c);

    // 1) EI = img_feat @ W_img^T + b_img           (512 x 1024 x 4096)
    {
        dim3 grid(HID / 128, NB / 128);
        sgemm_nt_bias<<<grid, 256>>>(img_feat, W_img, b_img, EI, NB, HID, IMGD);
    }

    // 2) assemble sequence X
    {
        dim3 grid(SEQ, NB);
        assemble_X<<<grid, EMBD / 4>>>(questions, emb, EI, first_w, X);
    }

    // 3) GX = X @ W_ih^T + b_ih                    (25088 x 4096 x 1024)
    {
        dim3 grid(G4 / 128, (SEQ * NB) / 128);
        sgemm_nt_bias<<<grid, 256>>>(X, W_ih, b_ih, GX, SEQ * NB, G4, EMBD);
    }

    // 4) zero state
    zero_hc<<<(NB * HID) / 256, 256>>>(h, c);

    // 5) recurrence
    for (int t = 0; t < SEQ; t++) {
        dim3 grid(G4 / 128, NB / 128);
        sgemm_nt_bias<<<grid, 256>>>(h, W_hh, b_hh, HW, NB, G4, HID);
        lstm_cell<<<(NB * HID) / 256, 256>>>(GX + (size_t)t * NB * G4, HW,
                                             c, h, hs_out, t);
    }

    // 6) output = h @ W_out^T + b_out              (512 x 32000 x 1024)
    {
        dim3 grid(VOC / 128, NB / 128);
        sgemm_nt_bias<<<grid, 256>>>(h, W_out, b_out, out, NB, VOC, HID);
    }
}

// round 3
// speedup vs baseline: 3.2648x; 3.2648x over previous
#include <cuda_runtime.h>
#include <cuda_bf16.h>
#include <math.h>
#include <stdint.h>

// ---------------------------------------------------------------------------
// VisLSTM on tensor cores (tf32 mma.sync), sm_103a.
//   x_t @ W_ih^T batched into one 25088x4096x1024 GEMM; only h @ W_hh^T
//   (512x4096x1024) is sequential (49 steps).
// ---------------------------------------------------------------------------

#define NB    512
#define TT    48
#define SEQ   49
#define EMBD  1024
#define HID   1024
#define G4    4096
#define IMGD  4096
#define VOC   32000

// Scratch (static device globals; allocation-free per harness rules)
__device__ float g_X [(size_t)SEQ * NB * EMBD];
__device__ float g_GX[(size_t)SEQ * NB * G4];
__device__ float g_EI[(size_t)NB * HID];
__device__ float g_HW[(size_t)NB * G4];
__device__ float g_h [(size_t)NB * HID];
__device__ float g_c [(size_t)NB * HID];

// ---------------------------------------------------------------------------
// helpers
// ---------------------------------------------------------------------------
__device__ __forceinline__ void cp16(void* s, const void* g) {
    uint32_t sa = (uint32_t)__cvta_generic_to_shared(s);
    asm volatile("cp.async.cg.shared.global [%0], [%1], 16;" :: "r"(sa), "l"(g));
}
__device__ __forceinline__ uint32_t f2tf(float x) {
    uint32_t r;
    asm("cvt.rna.tf32.f32 %0, %1;" : "=r"(r) : "f"(x));
    return r;
}
__device__ __forceinline__ void mma_tf32(float* c, const uint32_t* a, const uint32_t* b) {
    asm volatile(
        "mma.sync.aligned.m16n8k8.row.col.f32.tf32.tf32.f32 "
        "{%0,%1,%2,%3}, {%4,%5,%6,%7}, {%8,%9}, {%0,%1,%2,%3};"
        : "+f"(c[0]), "+f"(c[1]), "+f"(c[2]), "+f"(c[3])
        : "r"(a[0]), "r"(a[1]), "r"(a[2]), "r"(a[3]), "r"(b[0]), "r"(b[1]));
}

// ---------------------------------------------------------------------------
// TF32 GEMM: C[M,N] = A[M,K] @ B[N,K]^T + bias[N]
// Requires M%128==0, N%128==0, K%16==0 (true for all calls here).
// 128x128 CTA tile, BK=16 double-buffered (cp.async), 8 warps of 64x32.
// ---------------------------------------------------------------------------
__global__ __launch_bounds__(256)
void tf32_gemm_nt_bias(const float* __restrict__ A, const float* __restrict__ B,
                       const float* __restrict__ bias, float* __restrict__ C,
                       int M, int N, int K)
{
    __shared__ float As[2][128][20];   // padded stride 20: conflict-free, 16B-aligned rows
    __shared__ float Bs[2][128][20];

    const int tid  = threadIdx.x;
    const int wid  = tid >> 5;
    const int lane = tid & 31;
    const int brow = blockIdx.y * 128;
    const int bcol = blockIdx.x * 128;
    const int wm = (wid & 1) * 64;     // warp row offset
    const int wn = (wid >> 1) * 32;    // warp col offset

    const float* Abase = A + (size_t)brow * K;
    const float* Bbase = B + (size_t)bcol * K;

    float acc[4][4][4];
    #pragma unroll
    for (int mt = 0; mt < 4; mt++)
        #pragma unroll
        for (int nt = 0; nt < 4; nt++)
            #pragma unroll
            for (int r = 0; r < 4; r++) acc[mt][nt][r] = 0.f;

    const int ntiles = K >> 4;

    // prologue: tile 0 into buffer 0
    {
        #pragma unroll
        for (int i = 0; i < 2; i++) {
            int idx = tid + i * 256;
            int r = idx >> 2, cg = (idx & 3) * 4;
            cp16(&As[0][r][cg], Abase + (size_t)r * K + cg);
            cp16(&Bs[0][r][cg], Bbase + (size_t)r * K + cg);
        }
        asm volatile("cp.async.commit_group;");
    }

    const int r0 = lane >> 2;
    const int c0 = lane & 3;

    for (int kt = 0; kt < ntiles; kt++) {
        const int buf = kt & 1;
        if (kt + 1 < ntiles) {
            const int nb_ = buf ^ 1;
            const int koff = (kt + 1) << 4;
            #pragma unroll
            for (int i = 0; i < 2; i++) {
                int idx = tid + i * 256;
                int r = idx >> 2, cg = (idx & 3) * 4;
                cp16(&As[nb_][r][cg], Abase + (size_t)r * K + koff + cg);
                cp16(&Bs[nb_][r][cg], Bbase + (size_t)r * K + koff + cg);
            }
            asm volatile("cp.async.commit_group;");
            asm volatile("cp.async.wait_group 1;");
        } else {
            asm volatile("cp.async.wait_group 0;");
        }
        __syncthreads();

        #pragma unroll
        for (int kk = 0; kk < 16; kk += 8) {
            uint32_t afr[4][4];
            uint32_t bfr[4][2];
            #pragma unroll
            for (int mt = 0; mt < 4; mt++) {
                const int rb = wm + mt * 16;
                afr[mt][0] = f2tf(As[buf][rb + r0][kk + c0]);
                afr[mt][1] = f2tf(As[buf][rb + r0 + 8][kk + c0]);
                afr[mt][2] = f2tf(As[buf][rb + r0][kk + c0 + 4]);
                afr[mt][3] = f2tf(As[buf][rb + r0 + 8][kk + c0 + 4]);
            }
            #pragma unroll
            for (int nt = 0; nt < 4; nt++) {
                const int nb2 = wn + nt * 8;
                bfr[nt][0] = f2tf(Bs[buf][nb2 + r0][kk + c0]);
                bfr[nt][1] = f2tf(Bs[buf][nb2 + r0][kk + c0 + 4]);
            }
            #pragma unroll
            for (int mt = 0; mt < 4; mt++)
                #pragma unroll
                for (int nt = 0; nt < 4; nt++)
                    mma_tf32(acc[mt][nt], afr[mt], bfr[nt]);
        }
        __syncthreads();
    }

    // epilogue
    #pragma unroll
    for (int mt = 0; mt < 4; mt++) {
        #pragma unroll
        for (int nt = 0; nt < 4; nt++) {
            const int row = brow + wm + mt * 16 + r0;
            const int col = bcol + wn + nt * 8 + 2 * c0;
            float bv0 = bias ? bias[col]     : 0.f;
            float bv1 = bias ? bias[col + 1] : 0.f;
            float2 v0 = make_float2(acc[mt][nt][0] + bv0, acc[mt][nt][1] + bv1);
            float2 v1 = make_float2(acc[mt][nt][2] + bv0, acc[mt][nt][3] + bv1);
            *reinterpret_cast<float2*>(C + (size_t)row * N + col)       = v0;
            *reinterpret_cast<float2*>(C + (size_t)(row + 8) * N + col) = v1;
        }
    }
}

// ---------------------------------------------------------------------------
// sequence assembly
// ---------------------------------------------------------------------------
__global__ void assemble_X(const int* __restrict__ questions,
                           const float* __restrict__ emb,
                           const float* __restrict__ EI,
                           const int* __restrict__ first_words,
                           float* __restrict__ X)
{
    const int slot = blockIdx.x;   // 0..48
    const int n    = blockIdx.y;   // 0..511
    const int fw   = (*first_words) != 0;
    const int img_slot = fw ? 0 : TT;

    const float* src;
    if (slot == img_slot) {
        src = EI + (size_t)n * HID;
    } else {
        const int t = fw ? (slot - 1) : slot;
        const int q = questions[n * TT + t];
        src = emb + (size_t)q * EMBD;
    }
    float4 v = reinterpret_cast<const float4*>(src)[threadIdx.x];
    reinterpret_cast<float4*>(X + ((size_t)slot * NB + n) * EMBD)[threadIdx.x] = v;
}

__global__ void zero_hc(float* __restrict__ h, float* __restrict__ c)
{
    int i = blockIdx.x * blockDim.x + threadIdx.x;
    h[i] = 0.f;
    c[i] = 0.f;
}

// ---------------------------------------------------------------------------
// LSTM pointwise cell
// ---------------------------------------------------------------------------
__global__ void lstm_cell(const float* __restrict__ GX_t,
                          const float* __restrict__ HW,
                          float* __restrict__ c, float* __restrict__ h,
                          float* __restrict__ hs_out, int t)
{
    const int idx = blockIdx.x * blockDim.x + threadIdx.x;
    const int n = idx >> 10;
    const int j = idx & 1023;
    const size_t base = (size_t)n * G4;

    const float gi = GX_t[base + j]           + HW[base + j];
    const float gf = GX_t[base + HID + j]     + HW[base + HID + j];
    const float gg = GX_t[base + 2 * HID + j] + HW[base + 2 * HID + j];
    const float go = GX_t[base + 3 * HID + j] + HW[base + 3 * HID + j];

    const float i_ = 1.f / (1.f + expf(-gi));
    const float f_ = 1.f / (1.f + expf(-gf));
    const float g_ = tanhf(gg);
    const float o_ = 1.f / (1.f + expf(-go));

    const float cc = f_ * c[idx] + i_ * g_;
    const float hh = o_ * tanhf(cc);
    c[idx] = cc;
    h[idx] = hh;
    hs_out[((size_t)n * SEQ + t) * HID + j] = hh;
}

// ---------------------------------------------------------------------------
// Launch
// ---------------------------------------------------------------------------
extern "C" void kernel_launch(void* const* d_in, const int* in_sizes, int n_in,
                              void* d_out, int out_size)
{
    const int*   questions = (const int*)  d_in[0];
    const float* img_feat  = (const float*)d_in[1];
    const float* emb       = (const float*)d_in[2];
    const float* W_img     = (const float*)d_in[3];
    const float* b_img     = (const float*)d_in[4];
    const float* W_ih      = (const float*)d_in[5];
    const float* W_hh      = (const float*)d_in[6];
    const float* b_ih      = (const float*)d_in[7];
    const float* b_hh      = (const float*)d_in[8];
    const float* W_out     = (const float*)d_in[9];
    const float* b_out     = (const float*)d_in[10];
    const int*   first_w   = (const int*)  d_in[11];

    float* out    = (float*)d_out;             // [512,32000]
    float* hs_out = out + (size_t)NB * VOC;    // [512,49,1024]

    float *X, *GX, *EI, *HW, *h, *c;
    cudaGetSymbolAddress((void**)&X,  g_X);
    cudaGetSymbolAddress((void**)&GX, g_GX);
    cudaGetSymbolAddress((void**)&EI, g_EI);
    cudaGetSymbolAddress((void**)&HW, g_HW);
    cudaGetSymbolAddress((void**)&h,  g_h);
    cudaGetSymbolAddress((void**)&c,  g_c);

    // 1) EI = img_feat @ W_img^T + b_img           (512 x 1024 x 4096)
    {
        dim3 grid(HID / 128, NB / 128);
        tf32_gemm_nt_bias<<<grid, 256>>>(img_feat, W_img, b_img, EI, NB, HID, IMGD);
    }

    // 2) assemble sequence X
    {
        dim3 grid(SEQ, NB);
        assemble_X<<<grid, EMBD / 4>>>(questions, emb, EI, first_w, X);
    }

    // 3) GX = X @ W_ih^T + b_ih                    (25088 x 4096 x 1024)
    {
        dim3 grid(G4 / 128, (SEQ * NB) / 128);
        tf32_gemm_nt_bias<<<grid, 256>>>(X, W_ih, b_ih, GX, SEQ * NB, G4, EMBD);
    }

    // 4) zero state
    zero_hc<<<(NB * HID) / 256, 256>>>(h, c);

    // 5) recurrence
    for (int t = 0; t < SEQ; t++) {
        dim3 grid(G4 / 128, NB / 128);
        tf32_gemm_nt_bias<<<grid, 256>>>(h, W_hh, b_hh, HW, NB, G4, HID);
        lstm_cell<<<(NB * HID) / 256, 256>>>(GX + (size_t)t * NB * G4, HW,
                                             c, h, hs_out, t);
    }

    // 6) output = h @ W_out^T + b_out              (512 x 32000 x 1024)
    {
        dim3 grid(VOC / 128, NB / 128);
        tf32_gemm_nt_bias<<<grid, 256>>>(h, W_out, b_out, out, NB, VOC, HID);
    }
}